// round 8
// baseline (speedup 1.0000x reference)
#include <cuda_runtime.h>
#include <cstdint>

// Space-to-depth k=2: in [32, 224, 224, 64] f32 -> out [32, 112, 112, 256]
// out[b, ho, wo, kh*128 + kw*64 + c] = in[b, 2*ho+kh, 2*wo+kw, c]
//
// Chunk view (float4 units, C4=16 float4s/pixel):
//   input row-pair (b, 2ho..2ho+1) and output row (b, ho) are both 7168
//   contiguous float4s starting at the SAME offset chunk*7168 (chunk=b*112+ho).
// Within a chunk, output-local offset o (0..7167) maps to input-local:
//   in_off = ((o>>5)&1)*3584 + (o>>6)*32 + (o&31)
// Warp of 32 consecutive o -> one contiguous 512B load + one 512B store.
//
// R8: persistent grid-stride kernel. Grid = 148 SMs * 8 CTAs = 1184 resident
// CTAs (256 thr, ~26 regs -> thread-limited at 8/SM), each looping over
// tiles of 1024 float4s (7 tiles per chunk, 25088 tiles total). Eliminates
// all wave transitions / wave-tail DRAM drain. Body unchanged from R5:
// MLP=4, streaming hints, pure bit-math addressing.

static constexpr int      THREADS   = 256;
static constexpr int      ITEMS     = 4;                 // float4s per thread
static constexpr unsigned TILE_F4   = THREADS * ITEMS;   // 1024
static constexpr unsigned CHUNK_F4  = 7168;              // 2*224*16 = 112*64
static constexpr unsigned TILES_PER_CHUNK = 7;           // 7*1024 = 7168
static constexpr unsigned N_TILES   = 32u * 112u * TILES_PER_CHUNK;  // 25088
static constexpr unsigned GRID      = 148u * 8u;         // 1184 persistent CTAs

__global__ void __launch_bounds__(THREADS, 8)
s2d_kernel(const float4* __restrict__ in, float4* __restrict__ out)
{
    const unsigned tid = threadIdx.x;

    for (unsigned tile = blockIdx.x; tile < N_TILES; tile += GRID) {
        const unsigned chunk = tile / TILES_PER_CHUNK;
        const unsigned bx    = tile - chunk * TILES_PER_CHUNK;   // 0..6
        const unsigned base  = chunk * CHUNK_F4;
        const unsigned o0    = bx * TILE_F4 + tid;               // 0..7167

        // c4 bits (o & 63) are invariant across the 4 items (stride 256)
        const unsigned in0  = base + ((o0 >> 5) & 1u) * 3584u
                                   + (o0 >> 6) * 32u
                                   + (o0 & 31u);
        const unsigned out0 = base + o0;

        float4 v[ITEMS];
#pragma unroll
        for (int j = 0; j < ITEMS; j++)
            v[j] = __ldcs(in + in0 + (unsigned)j * 128u);
#pragma unroll
        for (int j = 0; j < ITEMS; j++)
            __stcs(out + out0 + (unsigned)j * 256u, v[j]);
    }
}

extern "C" void kernel_launch(void* const* d_in, const int* in_sizes, int n_in,
                              void* d_out, int out_size)
{
    (void)in_sizes; (void)n_in; (void)out_size;
    const float4* in  = (const float4*)d_in[0];
    float4*       out = (float4*)d_out;

    s2d_kernel<<<GRID, THREADS>>>(in, out);
}

// round 9
// speedup vs baseline: 1.1295x; 1.1295x over previous
#include <cuda_runtime.h>
#include <cstdint>

// Space-to-depth k=2: in [32, 224, 224, 64] f32 -> out [32, 112, 112, 256]
// out[b, ho, wo, kh*128 + kw*64 + c] = in[b, 2*ho+kh, 2*wo+kw, c]
//
// Chunk view (float4 units, C4=16 float4s/pixel):
//   input row-pair (b, 2ho..2ho+1) and output row (b, ho) are both 7168
//   contiguous float4s starting at the SAME offset chunk*7168 (chunk=b*112+ho).
// Within a chunk, output-local offset o (0..7167) maps to input-local:
//   in_off = ((o>>5)&1)*3584 + (o>>6)*32 + (o&31)
// Warp of 32 consecutive o -> one contiguous 512B load + one 512B store.
//
// FINAL (R9 = R7, best measured config): one CTA per chunk. THREADS=896,
// ITEMS=8 (896*8 = 7168 exactly). All 8 LDG.128 issued before any STG ->
// MLP=8 per thread. Streaming cache hints (__ldcs/__stcs) keep the one-pass
// 822MB stream from churning L2.
//
// Convergence evidence: R1/R4/R5/R7 span occ 31-84%, MLP 1-8, issue 4-30%,
// all pinned at DRAM 84.4+-0.1% / ~6.69 TB/s combined = chip memory-system
// ceiling (path-independent LTS cap; TMA cannot exceed it). Traffic is
// irreducible (pure permutation, zero reuse). ~115us kernel / ~121us bench
// is the floor for this problem.

static constexpr int THREADS = 896;          // 28 warps
static constexpr int ITEMS   = 8;
static constexpr unsigned CHUNK_F4 = 7168;   // 2*224*16 = 112*64
static constexpr unsigned CHUNKS   = 32u * 112u;   // 3584

__global__ void __launch_bounds__(THREADS)
s2d_kernel(const float4* __restrict__ in, float4* __restrict__ out)
{
    const unsigned base = blockIdx.x * CHUNK_F4;
    const unsigned tid  = threadIdx.x;

    float4 v[ITEMS];
#pragma unroll
    for (int j = 0; j < ITEMS; j++) {
        const unsigned o      = tid + (unsigned)j * THREADS;          // 0..7167
        const unsigned in_off = ((o >> 5) & 1u) * 3584u
                              + (o >> 6) * 32u
                              + (o & 31u);
        v[j] = __ldcs(in + base + in_off);
    }
#pragma unroll
    for (int j = 0; j < ITEMS; j++) {
        const unsigned o = tid + (unsigned)j * THREADS;
        __stcs(out + base + o, v[j]);
    }
}

extern "C" void kernel_launch(void* const* d_in, const int* in_sizes, int n_in,
                              void* d_out, int out_size)
{
    (void)in_sizes; (void)n_in; (void)out_size;
    const float4* in  = (const float4*)d_in[0];
    float4*       out = (float4*)d_out;

    s2d_kernel<<<CHUNKS, THREADS>>>(in, out);
}

// round 10
// speedup vs baseline: 1.1316x; 1.0018x over previous
#include <cuda_runtime.h>
#include <cstdint>

// Space-to-depth k=2: in [32, 224, 224, 64] f32 -> out [32, 112, 112, 256]
// out[b, ho, wo, kh*128 + kw*64 + c] = in[b, 2*ho+kh, 2*wo+kw, c]
//
// Chunk view (float4 units, C4=16 float4s/pixel):
//   input row-pair (b, 2ho..2ho+1) and output row (b, ho) are both 7168
//   contiguous float4s starting at the SAME offset chunk*7168 (chunk=b*112+ho).
// Within a chunk, output-local offset o (0..7167) maps to input-local:
//   in_off = ((o>>5)&1)*3584 + (o>>6)*32 + (o&31)
// Warp of 32 consecutive o -> one contiguous 512B load + one 512B store.
//
// R10: high-occupancy + deep-MLP cell of the experiment matrix.
// THREADS=512, ITEMS=7 -> tile = 3584 float4s = half a chunk, 2 blocks per
// chunk, grid = 7168. Item stride 512 is a multiple of 64 -> c4 bits
// invariant: in_off advances by exactly 256, out by 512 per item (pure adds).
// ~54 regs, 512 thr -> 2 CTA/SM = 32 warps (67% occ) with MLP=7/thread:
// highest aggregate in-flight load count of any config tested.
// Streaming hints (__ldcs/__stcs) keep the one-pass 822MB stream out of L2.

static constexpr int      THREADS  = 512;
static constexpr int      ITEMS    = 7;
static constexpr unsigned TILE_F4  = THREADS * ITEMS;    // 3584 = half chunk
static constexpr unsigned CHUNK_F4 = 7168;               // 2*224*16 = 112*64
static constexpr unsigned GRID     = 32u * 112u * 2u;    // 7168 tiles

__global__ void __launch_bounds__(THREADS)
s2d_kernel(const float4* __restrict__ in, float4* __restrict__ out)
{
    const unsigned chunk = blockIdx.x >> 1;              // 0..3583
    const unsigned half  = blockIdx.x & 1u;              // 0..1
    const unsigned base  = chunk * CHUNK_F4;
    const unsigned o0    = half * TILE_F4 + threadIdx.x; // 0..7167

    // bits 0..8 of o are invariant across items (stride 512), so the
    // in/out offsets advance by constant 256 / 512 float4s per item.
    const unsigned in0  = base + ((o0 >> 5) & 1u) * 3584u
                               + (o0 >> 6) * 32u
                               + (o0 & 31u);
    const unsigned out0 = base + o0;

    float4 v[ITEMS];
#pragma unroll
    for (int j = 0; j < ITEMS; j++)
        v[j] = __ldcs(in + in0 + (unsigned)j * 256u);
#pragma unroll
    for (int j = 0; j < ITEMS; j++)
        __stcs(out + out0 + (unsigned)j * 512u, v[j]);
}

extern "C" void kernel_launch(void* const* d_in, const int* in_sizes, int n_in,
                              void* d_out, int out_size)
{
    (void)in_sizes; (void)n_in; (void)out_size;
    const float4* in  = (const float4*)d_in[0];
    float4*       out = (float4*)d_out;

    s2d_kernel<<<GRID, THREADS>>>(in, out);
}